// round 13
// baseline (speedup 1.0000x reference)
#include <cuda_runtime.h>
#include <math.h>

// Problem dims
#define B 8
#define S 4096
#define F 128
#define T 16
#define THRESH 0.1f
#define EPS 1e-8f

// Stats tiling (measured-stable shape: 512 blocks x 256 thr, 9.6us)
#define NCHUNK 64
#define TY 8
#define RUN 8
#define STATS_BLOCKS (NCHUNK * B)        // 512

// Zero slices: t in {2,5,8,11,14} per b -> 40 slices of 131072 f4 (2MB each).
#define F4_PER_SLICE (S * (F / 4))       // 131072
#define ZBLK_F4 2048                     // per zero-block: 2048 f4 = 32KB
#define ZBLKS_PER_SLICE (F4_PER_SLICE / ZBLK_F4)   // 64
#define NZSLICES (B * 5)                 // 40
#define ZERO_BLOCKS (NZSLICES * ZBLKS_PER_SLICE)   // 2560
#define MAIN_BLOCKS (B * S * (F / 4) / 256)        // 4096

// Scratch: per-(b,f) double accumulators (16KB). k_inv re-zeros for replays.
__device__ double g_sum[B * F];
__device__ double g_sumsq[B * F];
__device__ __align__(16) float g_inv[B * F];

// Writes all 40 zero t-slices (stat-independent 84MB). Runs on a forked
// stream, concurrent with the whole stats->inv->main pipeline.
__global__ void k_zero_slices(float4* __restrict__ out) {
    int z = blockIdx.x;                  // 0..2559
    int slice = z >> 6;                  // 0..39
    int off = (z & 63) * ZBLK_F4;
    int b = slice / 5;
    int t = 2 + 3 * (slice % 5);         // 2,5,8,11,14
    float4* dst = out + ((size_t)(b * T + t) * F4_PER_SLICE) + off + threadIdx.x;
    const float4 zero = make_float4(0.f, 0.f, 0.f, 0.f);
    #pragma unroll
    for (int k = 0; k < ZBLK_F4 / 256; k++)
        dst[k * 256] = zero;
}

// Stats: float4 loads, rolling prev in registers (9 loads / 8 rows).
__global__ void k_acc(const float4* __restrict__ x) {
    int f4 = threadIdx.x;     // 0..31
    int ty = threadIdx.y;     // 0..7
    int chunk = blockIdx.x & (NCHUNK - 1);
    int b = blockIdx.x >> 6;

    int s_start = chunk * (TY * RUN) + ty * RUN;
    const float4* p = x + (size_t)b * S * 32 + (size_t)s_start * 32 + f4;

    float4 prev = (s_start == 0) ? p[0] : p[-32];   // prepend: diff[0] = 0

    float4 s1 = make_float4(0.f, 0.f, 0.f, 0.f);
    float4 s2 = make_float4(0.f, 0.f, 0.f, 0.f);
    #pragma unroll
    for (int j = 0; j < RUN; j++) {
        float4 cur = *p;
        p += 32;
        float dx = cur.x - prev.x, dy = cur.y - prev.y;
        float dz = cur.z - prev.z, dw = cur.w - prev.w;
        s1.x += dx; s1.y += dy; s1.z += dz; s1.w += dw;
        s2.x += dx * dx; s2.y += dy * dy; s2.z += dz * dz; s2.w += dw * dw;
        prev = cur;
    }

    __shared__ float4 sh1[TY][32];
    __shared__ float4 sh2[TY][32];
    sh1[ty][f4] = s1;
    sh2[ty][f4] = s2;
    __syncthreads();

    if (ty == 0) {
        float4 t1 = make_float4(0.f, 0.f, 0.f, 0.f);
        #pragma unroll
        for (int j = 0; j < TY; j++) {
            float4 a = sh1[j][f4];
            t1.x += a.x; t1.y += a.y; t1.z += a.z; t1.w += a.w;
        }
        int idx = b * F + f4 * 4;
        atomicAdd(&g_sum[idx + 0], (double)t1.x);
        atomicAdd(&g_sum[idx + 1], (double)t1.y);
        atomicAdd(&g_sum[idx + 2], (double)t1.z);
        atomicAdd(&g_sum[idx + 3], (double)t1.w);
    } else if (ty == 1) {
        float4 t2 = make_float4(0.f, 0.f, 0.f, 0.f);
        #pragma unroll
        for (int j = 0; j < TY; j++) {
            float4 c = sh2[j][f4];
            t2.x += c.x; t2.y += c.y; t2.z += c.z; t2.w += c.w;
        }
        int idx = b * F + f4 * 4;
        atomicAdd(&g_sumsq[idx + 0], (double)t2.x);
        atomicAdd(&g_sumsq[idx + 1], (double)t2.y);
        atomicAdd(&g_sumsq[idx + 2], (double)t2.z);
        atomicAdd(&g_sumsq[idx + 3], (double)t2.w);
    }
}

__global__ void k_inv() {
    int i = blockIdx.x * blockDim.x + threadIdx.x;
    if (i < B * F) {
        double m = g_sum[i] / (double)S;
        double var = g_sumsq[i] / (double)S - m * m;
        if (var < 0.0) var = 0.0;
        float sd = (float)sqrt(var);
        g_inv[i] = 1.0f / (sd + EPS);
        g_sum[i] = 0.0;     // re-zero for next call / graph replay
        g_sumsq[i] = 0.0;
    }
}

// Pos/neg expansion: 11 stores per thread (zero slices handled elsewhere).
__global__ void k_main_pn(const float4* __restrict__ x, float4* __restrict__ out) {
    int i = blockIdx.x * 256 + threadIdx.x;  // 0 .. B*S*(F/4)-1
    int f4 = i & 31;
    int s  = (i >> 5) & 4095;
    int b  = i >> 17;

    float4 cur = x[i];
    float4 prv = (s == 0) ? cur : x[i - 32];

    const float4 inv4 = *reinterpret_cast<const float4*>(&g_inv[b * F + f4 * 4]);

    float ndx = (cur.x - prv.x) * inv4.x;
    float ndy = (cur.y - prv.y) * inv4.y;
    float ndz = (cur.z - prv.z) * inv4.z;
    float ndw = (cur.w - prv.w) * inv4.w;

    float4 pos, neg;
    pos.x = (ndx >=  THRESH) ? 1.f : 0.f;
    pos.y = (ndy >=  THRESH) ? 1.f : 0.f;
    pos.z = (ndz >=  THRESH) ? 1.f : 0.f;
    pos.w = (ndw >=  THRESH) ? 1.f : 0.f;
    neg.x = (-ndx >= THRESH) ? 1.f : 0.f;
    neg.y = (-ndy >= THRESH) ? 1.f : 0.f;
    neg.z = (-ndz >= THRESH) ? 1.f : 0.f;
    neg.w = (-ndw >= THRESH) ? 1.f : 0.f;

    const size_t tstride = (size_t)S * 32;
    size_t obase = ((size_t)b * T * S + s) * 32 + f4;

    #pragma unroll
    for (int t = 0; t < T; t++) {
        int ph = t % 3;
        if (ph == 2) continue;                      // zeros written on stream 2
        out[obase + (size_t)t * tstride] = (ph == 0) ? pos : neg;
    }
}

extern "C" void kernel_launch(void* const* d_in, const int* in_sizes, int n_in,
                              void* d_out, int out_size) {
    const float* x = (const float*)d_in[0];
    float* out = (float*)d_out;

    // Fork-join: zero slices run on a parallel stream, concurrent with the
    // stats -> inv -> main pipeline. Documented capture-compatible pattern.
    // Stream/events are host objects, intentionally not destroyed (capture is
    // still active when kernel_launch returns; a handful of calls total).
    cudaStream_t s2;
    cudaStreamCreateWithFlags(&s2, cudaStreamNonBlocking);
    cudaEvent_t evFork, evJoin;
    cudaEventCreateWithFlags(&evFork, cudaEventDisableTiming);
    cudaEventCreateWithFlags(&evJoin, cudaEventDisableTiming);

    cudaEventRecord(evFork, 0);
    cudaStreamWaitEvent(s2, evFork, 0);
    k_zero_slices<<<ZERO_BLOCKS, 256, 0, s2>>>((float4*)out);
    cudaEventRecord(evJoin, s2);

    dim3 bt(32, TY);
    k_acc<<<STATS_BLOCKS, bt>>>((const float4*)x);
    k_inv<<<1, 1024>>>();
    k_main_pn<<<MAIN_BLOCKS, 256>>>((const float4*)x, (float4*)out);

    cudaStreamWaitEvent(0, evJoin, 0);   // output complete only after zeros land
}

// round 14
// speedup vs baseline: 1.0403x; 1.0403x over previous
#include <cuda_runtime.h>
#include <math.h>

// Problem dims
#define B 8
#define S 4096
#define F 128
#define T 16
#define THRESH 0.1f
#define EPS 1e-8f

// Stats tiling (measured-stable shape)
#define NCHUNK 64
#define TY 8
#define RUN 8
#define STATS_BLOCKS (NCHUNK * B)        // 512

// Zero slices: t in {2,5,8,11,14} per b -> 40 slices of 131072 f4 (2MB each).
// All 40 in k_pre (R10: measured best; moving them to main costs full BW).
#define F4_PER_SLICE (S * (F / 4))       // 131072
#define ZBLK_F4 2048                     // per zero-block: 2048 f4 = 32KB
#define ZBLKS_PER_SLICE (F4_PER_SLICE / ZBLK_F4)   // 64
#define NZSLICES (B * 5)                 // 40
#define ZERO_BLOCKS (NZSLICES * ZBLKS_PER_SLICE)   // 2560
#define PRE_BLOCKS (STATS_BLOCKS + ZERO_BLOCKS)    // 3072
#define MAIN_BLOCKS (B * S * (F / 4) / 256)        // 4096

// Scratch: per-(b,f) double accumulators (16KB). k_inv re-zeros for replays.
__device__ double g_sum[B * F];
__device__ double g_sumsq[B * F];
__device__ __align__(16) float g_inv[B * F];

// Fused prologue: blocks [0,512) = diff stats (atomics); blocks [512,3072)
// write the 40 zero t-slices with EVICT-FIRST stores so the 84MB zero stream
// does not evict the 16MB input from L2 (k_main re-reads the input; keeping
// it L2-resident removes ~17MB of DRAM reads).
__global__ void k_pre(const float4* __restrict__ x, float4* __restrict__ out) {
    int f4 = threadIdx.x;     // 0..31
    int ty = threadIdx.y;     // 0..7
    int tid = ty * 32 + f4;   // 0..255
    int bid = blockIdx.x;

    if (bid >= STATS_BLOCKS) {
        // ---- zero-writer half (evict-first stores) ----
        int z = bid - STATS_BLOCKS;              // 0..2559
        int slice = z >> 6;                      // 0..39
        int off = (z & 63) * ZBLK_F4;
        int b = slice / 5;
        int t = 2 + 3 * (slice % 5);             // 2,5,8,11,14
        float4* dst = out + ((size_t)(b * T + t) * F4_PER_SLICE) + off + tid;
        const float4 zero = make_float4(0.f, 0.f, 0.f, 0.f);
        #pragma unroll
        for (int k = 0; k < ZBLK_F4 / 256; k++)  // 8 stores, 256-f4 stride
            __stcs(&dst[k * 256], zero);
        return;
    }

    // ---- stats half (measured shape, unchanged) ----
    int chunk = bid & (NCHUNK - 1);
    int b = bid >> 6;

    int s_start = chunk * (TY * RUN) + ty * RUN;
    const float4* p = x + (size_t)b * S * 32 + (size_t)s_start * 32 + f4;

    float4 prev = (s_start == 0) ? p[0] : p[-32];   // prepend: diff[0] = 0

    float4 s1 = make_float4(0.f, 0.f, 0.f, 0.f);
    float4 s2 = make_float4(0.f, 0.f, 0.f, 0.f);
    #pragma unroll
    for (int j = 0; j < RUN; j++) {
        float4 cur = *p;
        p += 32;
        float dx = cur.x - prev.x, dy = cur.y - prev.y;
        float dz = cur.z - prev.z, dw = cur.w - prev.w;
        s1.x += dx; s1.y += dy; s1.z += dz; s1.w += dw;
        s2.x += dx * dx; s2.y += dy * dy; s2.z += dz * dz; s2.w += dw * dw;
        prev = cur;
    }

    __shared__ float4 sh1[TY][32];
    __shared__ float4 sh2[TY][32];
    sh1[ty][f4] = s1;
    sh2[ty][f4] = s2;
    __syncthreads();

    if (ty == 0) {
        float4 t1 = make_float4(0.f, 0.f, 0.f, 0.f);
        #pragma unroll
        for (int j = 0; j < TY; j++) {
            float4 a = sh1[j][f4];
            t1.x += a.x; t1.y += a.y; t1.z += a.z; t1.w += a.w;
        }
        int idx = b * F + f4 * 4;
        atomicAdd(&g_sum[idx + 0], (double)t1.x);
        atomicAdd(&g_sum[idx + 1], (double)t1.y);
        atomicAdd(&g_sum[idx + 2], (double)t1.z);
        atomicAdd(&g_sum[idx + 3], (double)t1.w);
    } else if (ty == 1) {
        float4 t2 = make_float4(0.f, 0.f, 0.f, 0.f);
        #pragma unroll
        for (int j = 0; j < TY; j++) {
            float4 c = sh2[j][f4];
            t2.x += c.x; t2.y += c.y; t2.z += c.z; t2.w += c.w;
        }
        int idx = b * F + f4 * 4;
        atomicAdd(&g_sumsq[idx + 0], (double)t2.x);
        atomicAdd(&g_sumsq[idx + 1], (double)t2.y);
        atomicAdd(&g_sumsq[idx + 2], (double)t2.z);
        atomicAdd(&g_sumsq[idx + 3], (double)t2.w);
    }
}

__global__ void k_inv() {
    int i = blockIdx.x * blockDim.x + threadIdx.x;
    if (i < B * F) {
        double m = g_sum[i] / (double)S;
        double var = g_sumsq[i] / (double)S - m * m;
        if (var < 0.0) var = 0.0;
        float sd = (float)sqrt(var);
        g_inv[i] = 1.0f / (sd + EPS);
        g_sum[i] = 0.0;     // re-zero for next call / graph replay
        g_sumsq[i] = 0.0;
    }
}

// Pos/neg expansion: 11 plain stores per thread (zeros written by k_pre).
__global__ void k_main_pn(const float4* __restrict__ x, float4* __restrict__ out) {
    int i = blockIdx.x * 256 + threadIdx.x;  // 0 .. B*S*(F/4)-1
    int f4 = i & 31;
    int s  = (i >> 5) & 4095;
    int b  = i >> 17;

    float4 cur = x[i];
    float4 prv = (s == 0) ? cur : x[i - 32];

    const float4 inv4 = *reinterpret_cast<const float4*>(&g_inv[b * F + f4 * 4]);

    float ndx = (cur.x - prv.x) * inv4.x;
    float ndy = (cur.y - prv.y) * inv4.y;
    float ndz = (cur.z - prv.z) * inv4.z;
    float ndw = (cur.w - prv.w) * inv4.w;

    float4 pos, neg;
    pos.x = (ndx >=  THRESH) ? 1.f : 0.f;
    pos.y = (ndy >=  THRESH) ? 1.f : 0.f;
    pos.z = (ndz >=  THRESH) ? 1.f : 0.f;
    pos.w = (ndw >=  THRESH) ? 1.f : 0.f;
    neg.x = (-ndx >= THRESH) ? 1.f : 0.f;
    neg.y = (-ndy >= THRESH) ? 1.f : 0.f;
    neg.z = (-ndz >= THRESH) ? 1.f : 0.f;
    neg.w = (-ndw >= THRESH) ? 1.f : 0.f;

    const size_t tstride = (size_t)S * 32;
    size_t obase = ((size_t)b * T * S + s) * 32 + f4;

    #pragma unroll
    for (int t = 0; t < T; t++) {
        int ph = t % 3;
        if (ph == 2) continue;                      // zeros written by k_pre
        out[obase + (size_t)t * tstride] = (ph == 0) ? pos : neg;
    }
}

extern "C" void kernel_launch(void* const* d_in, const int* in_sizes, int n_in,
                              void* d_out, int out_size) {
    const float* x = (const float*)d_in[0];
    float* out = (float*)d_out;

    dim3 bt(32, TY);
    k_pre<<<PRE_BLOCKS, bt>>>((const float4*)x, (float4*)out);
    k_inv<<<1, 1024>>>();
    k_main_pn<<<MAIN_BLOCKS, 256>>>((const float4*)x, (float4*)out);
}